// round 8
// baseline (speedup 1.0000x reference)
#include <cuda_runtime.h>
#include <cuda_bf16.h>
#include <cstdint>

#define Bq 256      // queries
#define Dk 768      // feature dim
#define Nn 131072   // database rows
#define Lo 512      // output row length

#define MARGIN 0.2f
#define CAND_CAP 16384
#define NTILES 1024          // 128 db rows per tile

// smem layout (per buffer: q 128x144B, db 128x144B)
#define F_QH   0
#define F_DH   18432
#define F_BUF  36864
#define SM_INVN 73728        // 128 floats (512 B)
#define SM_TM   74240        // 128 x 2 u32 (1 KB)
#define SMEM_TOTAL 133120    // padded >113.5KB to force 1 CTA/SM (R4's proven regime)

__device__ __nv_bfloat16 g_qh[Bq * Dk];
__device__ float g_invn[Nn];
__device__ unsigned g_tmax[Bq * NTILES];        // per-(q,tile) bf16-sim max (sortable)
__device__ unsigned long long g_best2[Bq];      // exact argmax keys
__device__ int g_cand_count;
__device__ unsigned g_cand[CAND_CAP];           // (q << 10) | tile

// ---------------- helpers ----------------
__device__ __forceinline__ uint32_t smem_u32(const void* p) {
    uint32_t a;
    asm("{ .reg .u64 t; cvta.to.shared.u64 t, %1; cvt.u32.u64 %0, t; }"
        : "=r"(a) : "l"(p));
    return a;
}
__device__ __forceinline__ unsigned sortable32(float v) {
    unsigned u = __float_as_uint(v);
    return (u & 0x80000000u) ? ~u : (u | 0x80000000u);
}
__device__ __forceinline__ float unsortable32(unsigned s) {
    unsigned u = (s & 0x80000000u) ? (s & 0x7fffffffu) : ~s;
    return __uint_as_float(u);
}
__device__ __forceinline__ unsigned long long pack_key(float v, unsigned idx) {
    return ((unsigned long long)sortable32(v) << 32) | (unsigned)(~idx);
}
__device__ __forceinline__ uint32_t b2u(__nv_bfloat162 h) {
    return *reinterpret_cast<uint32_t*>(&h);
}
__device__ __forceinline__ void cp_async16(uint32_t dst, const void* src) {
    asm volatile("cp.async.ca.shared.global [%0], [%1], 16;"
                 :: "r"(dst), "l"(src) : "memory");
}
__device__ __forceinline__ void cp_commit() {
    asm volatile("cp.async.commit_group;" ::: "memory");
}
__device__ __forceinline__ void cp_wait_all() {
    asm volatile("cp.async.wait_group 0;" ::: "memory");
}
__device__ __forceinline__ void ldsm_x4(uint32_t* r, uint32_t a) {
    asm volatile("ldmatrix.sync.aligned.m8n8.x4.shared.b16 {%0,%1,%2,%3}, [%4];"
                 : "=r"(r[0]), "=r"(r[1]), "=r"(r[2]), "=r"(r[3]) : "r"(a));
}
__device__ __forceinline__ void mma16816(float* d, const uint32_t* a, const uint32_t* b) {
    asm volatile(
        "mma.sync.aligned.m16n8k16.row.col.f32.bf16.bf16.f32 "
        "{%0,%1,%2,%3},{%4,%5,%6,%7},{%8,%9},{%0,%1,%2,%3};"
        : "+f"(d[0]), "+f"(d[1]), "+f"(d[2]), "+f"(d[3])
        : "r"(a[0]), "r"(a[1]), "r"(a[2]), "r"(a[3]), "r"(b[0]), "r"(b[1]));
}

// ---------------- convert queries + init state ----------------
__global__ void convert_init_kernel(const float* __restrict__ x) {
    int i = blockIdx.x * 256 + threadIdx.x;
    g_qh[i] = __float2bfloat16(x[i]);
    if (blockIdx.x == 0) {
        g_best2[threadIdx.x] = 0ull;
        if (threadIdx.x == 0) g_cand_count = 0;
    }
}

// ---------------- pass 1: bf16 GEMM -> per-(q,tile) max only ----------------
// grid 1024: CTA = (n-tile of 256 rows) x (q-half). R4's proven mainloop.
__global__ void __launch_bounds__(256, 1) sim_kernel(const float* __restrict__ db) {
    extern __shared__ char smem[];
    const uint32_t sb32 = smem_u32(smem);
    const int tid  = threadIdx.x;
    const int lane = tid & 31;
    const int w    = tid >> 5;
    const int q0   = (blockIdx.x & 1) * 128;
    const int n0   = (blockIdx.x >> 1) * 256;
    const int qb   = (w & 3) * 32;     // 32 queries per warp
    const int nb   = (w >> 2) * 64;    // 64 db rows per warp
    float* s_invn  = (float*)(smem + SM_INVN);
    unsigned* s_tm = (unsigned*)(smem + SM_TM);   // [128][2]

    const int row  = tid >> 1;         // 0..127
    const int half = tid & 1;

#pragma unroll 1
    for (int nh = 0; nh < 2; nh++) {
        const int nbase = n0 + nh * 128;
        const int tileIdx = (blockIdx.x >> 1) * 2 + nh;
        float acc[2][8][4];
#pragma unroll
        for (int a = 0; a < 2; a++)
#pragma unroll
            for (int b = 0; b < 8; b++)
#pragma unroll
                for (int r = 0; r < 4; r++) acc[a][b][r] = 0.f;
        float ps = 0.f;

        // ---- prologue: prefetch chunk 0 ----
        float4 dreg[8];
        {
            const float4* dsrc = (const float4*)(db + (size_t)(nbase + row) * Dk + half * 32);
#pragma unroll
            for (int i = 0; i < 8; i++) dreg[i] = dsrc[i];
            const __nv_bfloat16* qsrc = g_qh + (size_t)(q0 + row) * Dk + half * 32;
            uint32_t qdst = sb32 + F_QH + row * 144 + half * 64;
#pragma unroll
            for (int i = 0; i < 4; i++) cp_async16(qdst + i * 16, qsrc + i * 8);
            cp_commit();
        }

#pragma unroll 1
        for (int c = 0; c < 12; c++) {
            const int bufo = (c & 1) * F_BUF;
            // 1. convert & store db chunk c from regs; fuse norms
            {
                char* ph = smem + bufo + F_DH + row * 144 + half * 64;
#pragma unroll
                for (int i = 0; i < 8; i++) {
                    float4 f = dreg[i];
                    ps = fmaf(f.x, f.x, fmaf(f.y, f.y, fmaf(f.z, f.z, fmaf(f.w, f.w, ps))));
                    __nv_bfloat162 h01 = __floats2bfloat162_rn(f.x, f.y);
                    __nv_bfloat162 h23 = __floats2bfloat162_rn(f.z, f.w);
                    *(uint2*)(ph + i * 8) = make_uint2(b2u(h01), b2u(h23));
                }
            }
            // 2. prefetch db chunk c+1 into regs
            if (c < 11) {
                const float4* dsrc = (const float4*)(db + (size_t)(nbase + row) * Dk +
                                                     (c + 1) * 64 + half * 32);
#pragma unroll
                for (int i = 0; i < 8; i++) dreg[i] = dsrc[i];
            }
            // 3. q chunk c arrived
            cp_wait_all();
            // 4. chunk c tiles complete across CTA
            __syncthreads();
            // 5. prefetch q chunk c+1 (buf[(c+1)&1] free: MMA(c-1) done before sync)
            if (c < 11) {
                const __nv_bfloat16* qsrc = g_qh + (size_t)(q0 + row) * Dk +
                                            (c + 1) * 64 + half * 32;
                uint32_t qdst = sb32 + ((c + 1) & 1) * F_BUF + F_QH + row * 144 + half * 64;
#pragma unroll
                for (int i = 0; i < 4; i++) cp_async16(qdst + i * 16, qsrc + i * 8);
                cp_commit();
            }
            // 6. MMA on chunk c
            const uint32_t sqh = sb32 + bufo + F_QH;
            const uint32_t sdh = sb32 + bufo + F_DH;
#pragma unroll
            for (int ks = 0; ks < 4; ks++) {
                uint32_t aH[2][4];
#pragma unroll
                for (int mi = 0; mi < 2; mi++) {
                    uint32_t ao = (uint32_t)((qb + mi * 16 + (lane & 15)) * 144 +
                                             ks * 32 + (lane >> 4) * 16);
                    ldsm_x4(aH[mi], sqh + ao);
                }
#pragma unroll
                for (int nip = 0; nip < 4; nip++) {
                    uint32_t bo = (uint32_t)((nb + nip * 16 + (lane & 7) +
                                              ((lane >> 4) & 1) * 8) * 144 +
                                             ks * 32 + ((lane >> 3) & 1) * 16);
                    uint32_t bh[4];
                    ldsm_x4(bh, sdh + bo);
#pragma unroll
                    for (int mi = 0; mi < 2; mi++)
#pragma unroll
                        for (int s = 0; s < 2; s++)
                            mma16816(acc[mi][nip * 2 + s], aH[mi], &bh[2 * s]);
                }
            }
        }
        __syncthreads();   // all MMAs done before smem reuse

        // ---- inverse norms for this 128-row tile ----
        {
            float s = ps + __shfl_xor_sync(0xffffffffu, ps, 1);
            if (!half) {
                float r = 1.0f / fmaxf(sqrtf(s), 1e-8f);
                s_invn[row] = r;
                g_invn[nbase + row] = r;   // duplicate across q-halves, same value
            }
        }
        __syncthreads();

        // ---- per-(q, warp 64-row slice) max -> smem -> per-(q,tile) max ----
#pragma unroll
        for (int mi = 0; mi < 2; mi++)
#pragma unroll
            for (int g8 = 0; g8 < 2; g8++) {
                const int ql = qb + mi * 16 + g8 * 8 + (lane >> 2);
                float m = -1e30f;
#pragma unroll
                for (int ni = 0; ni < 8; ni++)
#pragma unroll
                    for (int s = 0; s < 2; s++) {
                        int nl = nb + ni * 8 + (lane & 3) * 2 + s;
                        m = fmaxf(m, acc[mi][ni][g8 * 2 + s] * s_invn[nl]);
                    }
                m = fmaxf(m, __shfl_xor_sync(0xffffffffu, m, 1));
                m = fmaxf(m, __shfl_xor_sync(0xffffffffu, m, 2));
                if ((lane & 3) == 0) s_tm[ql * 2 + (w >> 2)] = sortable32(m);
            }
        __syncthreads();
        if (tid < 128) {
            unsigned a = s_tm[tid * 2], b = s_tm[tid * 2 + 1];
            g_tmax[(size_t)(q0 + tid) * NTILES + tileIdx] = a > b ? a : b;
        }
        __syncthreads();   // s_tm/s_invn reused next nh
    }
}

// ---------------- pass 2: per-query tile filter ----------------
__global__ void __launch_bounds__(256) reduce_kernel() {
    const int q = blockIdx.x;
    const int tid = threadIdx.x;
    __shared__ unsigned s_red[256];
    const unsigned* tm = g_tmax + (size_t)q * NTILES;

    unsigned m = 0;
    unsigned v[4];
#pragma unroll
    for (int i = 0; i < 4; i++) {
        v[i] = tm[tid + 256 * i];
        m = m > v[i] ? m : v[i];
    }
    s_red[tid] = m;
    __syncthreads();
#pragma unroll
    for (int s = 128; s; s >>= 1) {
        if (tid < s) {
            unsigned o = s_red[tid + s];
            if (o > s_red[tid]) s_red[tid] = o;
        }
        __syncthreads();
    }
    const float thr = unsortable32(s_red[0]) - MARGIN;
#pragma unroll
    for (int i = 0; i < 4; i++) {
        if (unsortable32(v[i]) >= thr) {
            int slot = atomicAdd(&g_cand_count, 1);
            if (slot < CAND_CAP)
                g_cand[slot] = ((unsigned)q << 10) | (unsigned)(tid + 256 * i);
        }
    }
}

// ---------------- pass 3: exact fp32 rescore of surviving tiles ----------------
__global__ void __launch_bounds__(128) rescore_kernel(const float* __restrict__ x,
                                                      const float* __restrict__ db) {
    __shared__ float xq[Dk];
    const int tid  = threadIdx.x;
    const int lane = tid & 31;
    const int warp = tid >> 5;
    int cnt = g_cand_count;
    if (cnt > CAND_CAP) cnt = CAND_CAP;

    for (int i = blockIdx.x; i < cnt; i += gridDim.x) {
        unsigned c = g_cand[i];
        unsigned q = c >> 10;
        unsigned t = c & 1023u;
        for (int j = tid; j < Dk; j += 128) xq[j] = x[(size_t)q * Dk + j];
        __syncthreads();
#pragma unroll 1
        for (int r = 0; r < 32; r++) {
            int n = (int)t * 128 + warp * 32 + r;
            const float* d = db + (size_t)n * Dk;
            float s = 0.f;
#pragma unroll
            for (int j = 0; j < 24; j++)
                s = fmaf(xq[j * 32 + lane], d[j * 32 + lane], s);
#pragma unroll
            for (int mm = 16; mm; mm >>= 1) s += __shfl_xor_sync(0xffffffffu, s, mm);
            if (lane == 0)
                atomicMax(&g_best2[q], pack_key(s * g_invn[n], (unsigned)n));
        }
        __syncthreads();   // xq reused next iteration
    }
}

// ---------------- gather ----------------
__global__ void gather_kernel(const float* __restrict__ y, float* __restrict__ out) {
    const int b = blockIdx.x;
    unsigned idx = ~((unsigned)(g_best2[b] & 0xffffffffull));
    const float4* src = (const float4*)(y + (size_t)idx * Lo);
    float4* dst = (float4*)(out + (size_t)b * Lo);
    dst[threadIdx.x] = src[threadIdx.x];
}

extern "C" void kernel_launch(void* const* d_in, const int* in_sizes, int n_in,
                              void* d_out, int out_size) {
    const float* imu = (const float*)d_in[0];
    const float* dbx = (const float*)d_in[1];
    const float* dby = (const float*)d_in[2];
    float* out = (float*)d_out;

    cudaFuncSetAttribute(sim_kernel, cudaFuncAttributeMaxDynamicSharedMemorySize,
                         SMEM_TOTAL);

    convert_init_kernel<<<Dk, 256>>>(imu);
    sim_kernel<<<1024, 256, SMEM_TOTAL>>>(dbx);
    reduce_kernel<<<Bq, 256>>>();
    rescore_kernel<<<1024, 128>>>(imu, dbx);
    gather_kernel<<<Bq, Lo / 4>>>(dby, out);
}

// round 9
// speedup vs baseline: 1.1779x; 1.1779x over previous
#include <cuda_runtime.h>
#include <cuda_bf16.h>
#include <cstdint>

#define Bq 256      // queries
#define Dk 768      // feature dim
#define Nn 131072   // database rows
#define Lo 512      // output row length

#define MARGIN 0.2f
#define CAND_CAP 16384
#define NT8 (Nn / 8)          // 16384 8-row groups

// smem layout (per buffer: q 128x144B, db 128x144B)
#define F_QH   0
#define F_DH   18432
#define F_BUF  36864
#define SM_INVN 73728         // 128 floats
#define SM_TM8  74240         // 128 q x 16 tile8 u32 = 8192 B
#define SMEM_TOTAL (SM_TM8 + 8192 + 32)   // ~82.5 KB -> 2 CTAs/SM

__device__ __nv_bfloat16 g_qh[Bq * Dk];
__device__ float g_invn[Nn];
__device__ unsigned g_tmax8[(size_t)Bq * NT8];  // per-(q, 8-row group) bf16-sim max
__device__ unsigned long long g_best2[Bq];      // exact argmax keys
__device__ int g_cand_count;
__device__ unsigned g_cand[CAND_CAP];           // (q << 14) | tile8

// ---------------- helpers ----------------
__device__ __forceinline__ uint32_t smem_u32(const void* p) {
    uint32_t a;
    asm("{ .reg .u64 t; cvta.to.shared.u64 t, %1; cvt.u32.u64 %0, t; }"
        : "=r"(a) : "l"(p));
    return a;
}
__device__ __forceinline__ unsigned sortable32(float v) {
    unsigned u = __float_as_uint(v);
    return (u & 0x80000000u) ? ~u : (u | 0x80000000u);
}
__device__ __forceinline__ float unsortable32(unsigned s) {
    unsigned u = (s & 0x80000000u) ? (s & 0x7fffffffu) : ~s;
    return __uint_as_float(u);
}
__device__ __forceinline__ unsigned long long pack_key(float v, unsigned idx) {
    return ((unsigned long long)sortable32(v) << 32) | (unsigned)(~idx);
}
__device__ __forceinline__ uint32_t b2u(__nv_bfloat162 h) {
    return *reinterpret_cast<uint32_t*>(&h);
}
__device__ __forceinline__ void cp_async16(uint32_t dst, const void* src) {
    asm volatile("cp.async.ca.shared.global [%0], [%1], 16;"
                 :: "r"(dst), "l"(src) : "memory");
}
__device__ __forceinline__ void cp_commit() {
    asm volatile("cp.async.commit_group;" ::: "memory");
}
__device__ __forceinline__ void cp_wait_all() {
    asm volatile("cp.async.wait_group 0;" ::: "memory");
}
__device__ __forceinline__ void ldsm_x4(uint32_t* r, uint32_t a) {
    asm volatile("ldmatrix.sync.aligned.m8n8.x4.shared.b16 {%0,%1,%2,%3}, [%4];"
                 : "=r"(r[0]), "=r"(r[1]), "=r"(r[2]), "=r"(r[3]) : "r"(a));
}
__device__ __forceinline__ void mma16816(float* d, const uint32_t* a, const uint32_t* b) {
    asm volatile(
        "mma.sync.aligned.m16n8k16.row.col.f32.bf16.bf16.f32 "
        "{%0,%1,%2,%3},{%4,%5,%6,%7},{%8,%9},{%0,%1,%2,%3};"
        : "+f"(d[0]), "+f"(d[1]), "+f"(d[2]), "+f"(d[3])
        : "r"(a[0]), "r"(a[1]), "r"(a[2]), "r"(a[3]), "r"(b[0]), "r"(b[1]));
}

// ---------------- convert queries + init state ----------------
__global__ void convert_init_kernel(const float* __restrict__ x) {
    int i = blockIdx.x * 256 + threadIdx.x;
    g_qh[i] = __float2bfloat16(x[i]);
    if (blockIdx.x == 0) {
        g_best2[threadIdx.x] = 0ull;
        if (threadIdx.x == 0) g_cand_count = 0;
    }
}

// ---------------- pass 1: bf16 GEMM -> per-(q, 8-row group) max ----------------
// grid 1024: CTA = (256-row n-tile) x (q-half); loops nh over two 128-row halves.
__global__ void __launch_bounds__(256, 2) sim_kernel(const float* __restrict__ db) {
    extern __shared__ char smem[];
    const uint32_t sb32 = smem_u32(smem);
    const int tid  = threadIdx.x;
    const int lane = tid & 31;
    const int w    = tid >> 5;
    const int q0   = (blockIdx.x & 1) * 128;
    const int n0   = (blockIdx.x >> 1) * 256;
    const int qb   = (w & 3) * 32;     // 32 queries per warp
    const int nb   = (w >> 2) * 64;    // 64 db rows per warp
    float* s_invn  = (float*)(smem + SM_INVN);
    unsigned* s_tm = (unsigned*)(smem + SM_TM8);   // [128 q][16 tile8]

    const int row  = tid >> 1;         // 0..127
    const int half = tid & 1;

#pragma unroll 1
    for (int nh = 0; nh < 2; nh++) {
        const int nbase = n0 + nh * 128;
        float acc[2][8][4];
#pragma unroll
        for (int a = 0; a < 2; a++)
#pragma unroll
            for (int b = 0; b < 8; b++)
#pragma unroll
                for (int r = 0; r < 4; r++) acc[a][b][r] = 0.f;
        float ps = 0.f;

        // converted db prefetch regs (bf16x2 packed: 16 u32 instead of 32 fp32)
        uint2 dreg[4];
        const float* drow = db + (size_t)(nbase + row) * Dk + half * 32;

        // ---- prologue: prefetch+convert chunk 0, cp.async q chunk 0 ----
#pragma unroll
        for (int i = 0; i < 4; i++) {
            float4 f0 = ((const float4*)drow)[2 * i];
            float4 f1 = ((const float4*)drow)[2 * i + 1];
            ps = fmaf(f0.x, f0.x, fmaf(f0.y, f0.y, fmaf(f0.z, f0.z, fmaf(f0.w, f0.w, ps))));
            ps = fmaf(f1.x, f1.x, fmaf(f1.y, f1.y, fmaf(f1.z, f1.z, fmaf(f1.w, f1.w, ps))));
            dreg[i].x = b2u(__floats2bfloat162_rn(f0.x, f0.y));
            dreg[i].y = b2u(__floats2bfloat162_rn(f0.z, f0.w));
            // pack second half into high regs via a second uint2 stored interleaved
            // (kept as separate temporaries below)
            // store immediately-converted second float4 into a rotating pair:
            // we use dreg2 array declared below
            ((uint2*)dreg)[i] = dreg[i];   // no-op keep
            // stash f1 converted
            // handled by dreg2:
            (void)f1;
        }
        // NOTE: to keep exactly 16 u32 of payload we use two arrays of uint2[4]
        uint2 dreg2[4];
        {
            // redo conversion for second float4s (loads hit L1; cheap, keeps regs low)
#pragma unroll
            for (int i = 0; i < 4; i++) {
                float4 f1 = ((const float4*)drow)[2 * i + 1];
                dreg2[i].x = b2u(__floats2bfloat162_rn(f1.x, f1.y));
                dreg2[i].y = b2u(__floats2bfloat162_rn(f1.z, f1.w));
            }
        }
        {
            const __nv_bfloat16* qsrc = g_qh + (size_t)(q0 + row) * Dk + half * 32;
            uint32_t qdst = sb32 + F_QH + row * 144 + half * 64;
#pragma unroll
            for (int i = 0; i < 4; i++) cp_async16(qdst + i * 16, qsrc + i * 8);
            cp_commit();
        }

#pragma unroll 1
        for (int c = 0; c < 12; c++) {
            const int bufo = (c & 1) * F_BUF;
            // 1. store converted db chunk c from regs
            {
                char* ph = smem + bufo + F_DH + row * 144 + half * 64;
#pragma unroll
                for (int i = 0; i < 4; i++) {
                    *(uint2*)(ph + i * 16)     = dreg[i];
                    *(uint2*)(ph + i * 16 + 8) = dreg2[i];
                }
            }
            // 2. prefetch + convert db chunk c+1 (overlaps MMA below via OOO issue)
            if (c < 11) {
                const float* dn = drow + (c + 1) * 64;
#pragma unroll
                for (int i = 0; i < 4; i++) {
                    float4 f0 = ((const float4*)dn)[2 * i];
                    float4 f1 = ((const float4*)dn)[2 * i + 1];
                    ps = fmaf(f0.x, f0.x, fmaf(f0.y, f0.y, fmaf(f0.z, f0.z, fmaf(f0.w, f0.w, ps))));
                    ps = fmaf(f1.x, f1.x, fmaf(f1.y, f1.y, fmaf(f1.z, f1.z, fmaf(f1.w, f1.w, ps))));
                    dreg[i].x  = b2u(__floats2bfloat162_rn(f0.x, f0.y));
                    dreg[i].y  = b2u(__floats2bfloat162_rn(f0.z, f0.w));
                    dreg2[i].x = b2u(__floats2bfloat162_rn(f1.x, f1.y));
                    dreg2[i].y = b2u(__floats2bfloat162_rn(f1.z, f1.w));
                }
            }
            // 3. q chunk c arrived
            cp_wait_all();
            __syncthreads();   // chunk c tiles complete
            // 4. issue q chunk c+1 into the other buffer
            if (c < 11) {
                const __nv_bfloat16* qsrc = g_qh + (size_t)(q0 + row) * Dk +
                                            (c + 1) * 64 + half * 32;
                uint32_t qdst = sb32 + ((c + 1) & 1) * F_BUF + F_QH + row * 144 + half * 64;
#pragma unroll
                for (int i = 0; i < 4; i++) cp_async16(qdst + i * 16, qsrc + i * 8);
                cp_commit();
            }
            // 5. MMA on chunk c
            const uint32_t sqh = sb32 + bufo + F_QH;
            const uint32_t sdh = sb32 + bufo + F_DH;
#pragma unroll
            for (int ks = 0; ks < 4; ks++) {
                uint32_t aH[2][4];
#pragma unroll
                for (int mi = 0; mi < 2; mi++) {
                    uint32_t ao = (uint32_t)((qb + mi * 16 + (lane & 15)) * 144 +
                                             ks * 32 + (lane >> 4) * 16);
                    ldsm_x4(aH[mi], sqh + ao);
                }
#pragma unroll
                for (int nip = 0; nip < 4; nip++) {
                    uint32_t bo = (uint32_t)((nb + nip * 16 + (lane & 7) +
                                              ((lane >> 4) & 1) * 8) * 144 +
                                             ks * 32 + ((lane >> 3) & 1) * 16);
                    uint32_t bh[4];
                    ldsm_x4(bh, sdh + bo);
#pragma unroll
                    for (int mi = 0; mi < 2; mi++)
#pragma unroll
                        for (int s = 0; s < 2; s++)
                            mma16816(acc[mi][nip * 2 + s], aH[mi], &bh[2 * s]);
                }
            }
            // no trailing sync: buffer reuse ordered by next chunk's sync
        }
        __syncthreads();   // all MMAs done before smem epilogue reuse

        // ---- inverse norms for this 128-row tile ----
        {
            float s = ps + __shfl_xor_sync(0xffffffffu, ps, 1);
            if (!half) {
                float r = 1.0f / fmaxf(sqrtf(s), 1e-8f);
                s_invn[row] = r;
                g_invn[nbase + row] = r;   // dup across q-halves, same value
            }
        }
        __syncthreads();

        // ---- per-(q, 8-row group) max -> smem ----
#pragma unroll
        for (int mi = 0; mi < 2; mi++)
#pragma unroll
            for (int g8 = 0; g8 < 2; g8++) {
                const int ql = qb + mi * 16 + g8 * 8 + (lane >> 2);
#pragma unroll
                for (int ni = 0; ni < 8; ni++) {
                    int nl0 = nb + ni * 8 + (lane & 3) * 2;
                    float m = fmaxf(acc[mi][ni][g8 * 2 + 0] * s_invn[nl0],
                                    acc[mi][ni][g8 * 2 + 1] * s_invn[nl0 + 1]);
                    m = fmaxf(m, __shfl_xor_sync(0xffffffffu, m, 1));
                    m = fmaxf(m, __shfl_xor_sync(0xffffffffu, m, 2));
                    if ((lane & 3) == 0)
                        s_tm[ql * 16 + (nb >> 3) + ni] = sortable32(m);
                }
            }
        __syncthreads();
        // coalesced write: each thread writes 8 consecutive u32 (32B)
        {
            const int ql = tid >> 1;
            const int hh = (tid & 1) * 8;
            uint4* dst = (uint4*)(g_tmax8 + (size_t)(q0 + ql) * NT8 + (nbase >> 3) + hh);
            const unsigned* src = s_tm + ql * 16 + hh;
            dst[0] = make_uint4(src[0], src[1], src[2], src[3]);
            dst[1] = make_uint4(src[4], src[5], src[6], src[7]);
        }
        __syncthreads();   // s_tm/s_invn reused next nh
    }
}

// ---------------- pass 2: per-query tile8 filter ----------------
__global__ void __launch_bounds__(256) reduce_kernel() {
    const int q = blockIdx.x;
    const int tid = threadIdx.x;
    __shared__ unsigned s_red[256];
    const unsigned* tm = g_tmax8 + (size_t)q * NT8;

    unsigned m = 0;
    unsigned v[64];
#pragma unroll
    for (int i = 0; i < 64; i++) {
        v[i] = tm[tid + 256 * i];          // coalesced
        m = m > v[i] ? m : v[i];
    }
    s_red[tid] = m;
    __syncthreads();
#pragma unroll
    for (int s = 128; s; s >>= 1) {
        if (tid < s) {
            unsigned o = s_red[tid + s];
            if (o > s_red[tid]) s_red[tid] = o;
        }
        __syncthreads();
    }
    const unsigned thr = sortable32(unsortable32(s_red[0]) - MARGIN);
#pragma unroll
    for (int i = 0; i < 64; i++) {
        if (v[i] >= thr) {
            int slot = atomicAdd(&g_cand_count, 1);
            if (slot < CAND_CAP)
                g_cand[slot] = ((unsigned)q << 14) | (unsigned)(tid + 256 * i);
        }
    }
}

// ---------------- pass 3: exact fp32 rescore (one warp per row, 8 rows/cand) ----
__global__ void __launch_bounds__(256) rescore_kernel(const float* __restrict__ x,
                                                      const float* __restrict__ db) {
    __shared__ float xq[Dk];
    const int tid  = threadIdx.x;
    const int lane = tid & 31;
    const int warp = tid >> 5;
    int cnt = g_cand_count;
    if (cnt > CAND_CAP) cnt = CAND_CAP;

    for (int i = blockIdx.x; i < cnt; i += gridDim.x) {
        unsigned c = g_cand[i];
        unsigned q = c >> 14;
        unsigned t = c & 16383u;
        for (int j = tid; j < Dk; j += 256) xq[j] = x[(size_t)q * Dk + j];
        __syncthreads();
        int n = (int)t * 8 + warp;
        const float* d = db + (size_t)n * Dk;
        float s = 0.f;
#pragma unroll
        for (int j = 0; j < 24; j++)
            s = fmaf(xq[j * 32 + lane], d[j * 32 + lane], s);
#pragma unroll
        for (int mm = 16; mm; mm >>= 1) s += __shfl_xor_sync(0xffffffffu, s, mm);
        if (lane == 0)
            atomicMax(&g_best2[q], pack_key(s * g_invn[n], (unsigned)n));
        __syncthreads();   // xq reused next iteration
    }
}

// ---------------- gather ----------------
__global__ void gather_kernel(const float* __restrict__ y, float* __restrict__ out) {
    const int b = blockIdx.x;
    unsigned idx = ~((unsigned)(g_best2[b] & 0xffffffffull));
    const float4* src = (const float4*)(y + (size_t)idx * Lo);
    float4* dst = (float4*)(out + (size_t)b * Lo);
    dst[threadIdx.x] = src[threadIdx.x];
}

extern "C" void kernel_launch(void* const* d_in, const int* in_sizes, int n_in,
                              void* d_out, int out_size) {
    const float* imu = (const float*)d_in[0];
    const float* dbx = (const float*)d_in[1];
    const float* dby = (const float*)d_in[2];
    float* out = (float*)d_out;

    cudaFuncSetAttribute(sim_kernel, cudaFuncAttributeMaxDynamicSharedMemorySize,
                         SMEM_TOTAL);

    convert_init_kernel<<<Dk, 256>>>(imu);
    sim_kernel<<<1024, 256, SMEM_TOTAL>>>(dbx);
    reduce_kernel<<<Bq, 256>>>();
    rescore_kernel<<<512, 256>>>(imu, dbx);
    gather_kernel<<<Bq, Lo / 4>>>(dby, out);
}